// round 4
// baseline (speedup 1.0000x reference)
#include <cuda_runtime.h>
#include <cuda_bf16.h>
#include <math.h>

#define BB 64
#define TT 512
#define EE 512
#define HH 1024
#define GG 4096   // 4*H
#define CC 4
#define NBLK 128  // persistent recurrence blocks

// ---------------------------------------------------------------------------
// Global scratch (static device arrays — no runtime allocation)
// ---------------------------------------------------------------------------
__device__ float g_xp[(size_t)TT * BB * GG];          // [T][B][4H] input projections
__device__ float g_h[BB * HH];                        // final hidden state
// h staged as bf16 hi/lo MMA A-fragments: [buf][ktile 64][mtile 4][hl 2][lane 32] x 16B
__device__ uint4 g_hstage[2][64 * 4 * 2 * 32];
__device__ unsigned g_flags[NBLK];                    // recurrence barrier flags

// xproj operands pre-converted to MMA fragment layout (bf16 hi/lo):
// A: [mtile 2048][ktile 32][hl 2][lane 32] x 16B   (rows m = t*64+b)
__device__ uint4 g_afrag[(size_t)2048 * 32 * 2 * 32];   // 64 MB
// B: [ktile 32][ntile16 256][hl 2][lane 32] x 16B
__device__ uint4 g_bfrag[(size_t)32 * 256 * 2 * 32];    // 8 MB

// ---------------------------------------------------------------------------
// helpers
// ---------------------------------------------------------------------------
__device__ __forceinline__ void cpasync16(unsigned dst, const void* src) {
    asm volatile("cp.async.cg.shared.global [%0], [%1], 16;" :: "r"(dst), "l"(src));
}
__device__ __forceinline__ uint4 lds128(unsigned addr) {
    uint4 v;
    asm volatile("ld.shared.v4.u32 {%0,%1,%2,%3}, [%4];"
                 : "=r"(v.x), "=r"(v.y), "=r"(v.z), "=r"(v.w) : "r"(addr));
    return v;
}
__device__ __forceinline__ void mma16816(float* d, const uint4& a, unsigned b0, unsigned b1) {
    asm volatile("mma.sync.aligned.m16n8k16.row.col.f32.bf16.bf16.f32 "
                 "{%0,%1,%2,%3}, {%4,%5,%6,%7}, {%8,%9}, {%0,%1,%2,%3};"
                 : "+f"(d[0]), "+f"(d[1]), "+f"(d[2]), "+f"(d[3])
                 : "r"(a.x), "r"(a.y), "r"(a.z), "r"(a.w), "r"(b0), "r"(b1));
}
__device__ __forceinline__ unsigned pack_hi(float x0, float x1) {
    unsigned h0 = (unsigned)__bfloat16_as_ushort(__float2bfloat16(x0));
    unsigned h1 = (unsigned)__bfloat16_as_ushort(__float2bfloat16(x1));
    return h0 | (h1 << 16);
}
__device__ __forceinline__ unsigned pack_lo(float x0, float x1) {
    float r0 = x0 - __bfloat162float(__float2bfloat16(x0));
    float r1 = x1 - __bfloat162float(__float2bfloat16(x1));
    unsigned h0 = (unsigned)__bfloat16_as_ushort(__float2bfloat16(r0));
    unsigned h1 = (unsigned)__bfloat16_as_ushort(__float2bfloat16(r1));
    return h0 | (h1 << 16);
}

// ---------------------------------------------------------------------------
// init: zero barrier flags + h(-1) staging buffer 0
// ---------------------------------------------------------------------------
__global__ void init_kernel() {
    int i = blockIdx.x * blockDim.x + threadIdx.x;
    if (i < NBLK) g_flags[i] = 0u;
    if (i < 64 * 4 * 2 * 32) g_hstage[0][i] = make_uint4(0u, 0u, 0u, 0u);
}

// ---------------------------------------------------------------------------
// conv_a: gather emb rows, convert to bf16 hi/lo A-fragment layout.
// One warp per (mtile, ktile) unit. 2048*32 = 65536 warps.
// Element (rr, kc) of a 16x16 tile: ln=((rr&7)<<2)+((kc&7)>>1),
//   reg=(((kc>>3)&1)<<1)+((rr>>3)&1), halfword=(kc&1).
// Inverse (lane l, reg r2, hw): rr=(l>>2)|((r2&1)<<3), kc=((l&3)<<1)|((r2>>1)<<3)|hw
// ---------------------------------------------------------------------------
__global__ __launch_bounds__(256) void conv_a_kernel(
        const int* __restrict__ tokens, const float* __restrict__ emb) {
    int gw = (blockIdx.x * 256 + threadIdx.x) >> 5;
    int lane = threadIdx.x & 31;
    int mt = gw >> 5;          // 0..2047
    int kt = gw & 31;          // 0..31
    // within this mtile, t is constant: m = mt*16+rr, t = m>>6 = mt>>2
    int t_ = mt >> 2;
    // two rows per lane: rr0 = lane>>2, rr1 = rr0+8
    int b0_ = ((mt & 3) << 4) + (lane >> 2);
    int b1_ = b0_ + 8;
    const float* er0 = emb + (size_t)tokens[b0_ * TT + t_] * EE + kt * 16;
    const float* er1 = emb + (size_t)tokens[b1_ * TT + t_] * EE + kt * 16;

    unsigned hi[4], lo[4];
#pragma unroll
    for (int r2 = 0; r2 < 4; r2++) {
        const float* er = (r2 & 1) ? er1 : er0;
        int kc0 = ((lane & 3) << 1) + ((r2 >> 1) << 3);
        float x0 = er[kc0], x1 = er[kc0 + 1];
        hi[r2] = pack_hi(x0, x1);
        lo[r2] = pack_lo(x0, x1);
    }
    size_t base = ((size_t)(mt * 32 + kt) * 2) * 32 + lane;
    g_afrag[base]      = make_uint4(hi[0], hi[1], hi[2], hi[3]);
    g_afrag[base + 32] = make_uint4(lo[0], lo[1], lo[2], lo[3]);
}

// ---------------------------------------------------------------------------
// conv_b: Wi -> bf16 hi/lo B-fragment layout. One warp per (ktile, ntile16).
// Element (n, kc): ln=((n&7)<<2)+((kc&7)>>1),
//   word=(((n>>3)&1)<<1)|((kc>>3)&1), halfword=(kc&1).
// Inverse (lane l, word w, hw): n=((w>>1)<<3)|(l>>2), kc=((l&3)<<1)|((w&1)<<3)|hw
// ---------------------------------------------------------------------------
__global__ __launch_bounds__(256) void conv_b_kernel(const float* __restrict__ Wi) {
    int gw = (blockIdx.x * 256 + threadIdx.x) >> 5;
    int lane = threadIdx.x & 31;
    int kt = gw >> 8;          // 0..31
    int nt = gw & 255;         // 0..255

    unsigned hi[4], lo[4];
#pragma unroll
    for (int w = 0; w < 4; w++) {
        int n  = ((w >> 1) << 3) + (lane >> 2);
        int kc0 = ((lane & 3) << 1) + ((w & 1) << 3);
        const float* p = Wi + (size_t)(kt * 16 + kc0) * GG + nt * 16 + n;
        float x0 = p[0], x1 = p[GG];
        hi[w] = pack_hi(x0, x1);
        lo[w] = pack_lo(x0, x1);
    }
    size_t base = ((size_t)(kt * 256 + nt) * 2) * 32 + lane;
    g_bfrag[base]      = make_uint4(hi[0], hi[1], hi[2], hi[3]);
    g_bfrag[base + 32] = make_uint4(lo[0], lo[1], lo[2], lo[3]);
}

// ---------------------------------------------------------------------------
// xgemm: XP = X @ Wi + bias via bf16 split-3 MMA.
// Block tile 128x128, K chunks of 32 (2 ktiles), double-buffered cp.async.
// Smem: A buf: [mt 8][kt 2][hl 2]x512B = 16KB; B buf: [kt 2][nt 8][hl 2]x512B.
// ---------------------------------------------------------------------------
#define XG_ABUF 16384
#define XG_BOFF 32768
#define XG_SMEM 65536

__global__ __launch_bounds__(256) void xgemm_kernel(const float* __restrict__ bias) {
    extern __shared__ char smem[];
    const unsigned smem_u32 = (unsigned)__cvta_generic_to_shared(smem);
    const int tid = threadIdx.x;
    const int warp = tid >> 5, lane = tid & 31;
    const int mq = warp & 1;        // 0..1 (64-row half)
    const int nq = warp >> 1;       // 0..3 (32-col quarter)
    const int bx = blockIdx.x, by = blockIdx.y;

    // cp.async assignment
    const bool isA = tid < 128;
    const int amt = (tid & 127) >> 4;      // 0..7 (mt for A, nt for B)
    const int sub = tid & 15;

    float acc[4][4][4];
#pragma unroll
    for (int i = 0; i < 4; i++)
#pragma unroll
        for (int j = 0; j < 4; j++)
#pragma unroll
            for (int q = 0; q < 4; q++) acc[i][j][q] = 0.f;

    // prefetch chunk 0
#pragma unroll
    for (int j = 0; j < 8; j++) {
        int q = sub * 8 + j;              // 0..127
        int kt = q >> 6, hl = (q >> 5) & 1, ln = q & 31;
        unsigned dst; const uint4* src;
        if (isA) {
            dst = smem_u32 + ((amt * 2 + kt) * 2 + hl) * 512 + ln * 16;
            src = g_afrag + (((size_t)(bx * 8 + amt) * 32 + kt) * 2 + hl) * 32 + ln;
        } else {
            dst = smem_u32 + XG_BOFF + ((kt * 8 + amt) * 2 + hl) * 512 + ln * 16;
            src = g_bfrag + (((size_t)kt * 256 + (by * 8 + amt)) * 2 + hl) * 32 + ln;
        }
        cpasync16(dst, src);
    }
    asm volatile("cp.async.commit_group;");

    for (int c = 0; c < 16; c++) {
        if (c < 15) {
            int buf = (c + 1) & 1;
#pragma unroll
            for (int j = 0; j < 8; j++) {
                int q = sub * 8 + j;
                int kt = q >> 6, hl = (q >> 5) & 1, ln = q & 31;
                int ktg = (c + 1) * 2 + kt;
                unsigned dst; const uint4* src;
                if (isA) {
                    dst = smem_u32 + buf * XG_ABUF + ((amt * 2 + kt) * 2 + hl) * 512 + ln * 16;
                    src = g_afrag + (((size_t)(bx * 8 + amt) * 32 + ktg) * 2 + hl) * 32 + ln;
                } else {
                    dst = smem_u32 + XG_BOFF + buf * XG_ABUF + ((kt * 8 + amt) * 2 + hl) * 512 + ln * 16;
                    src = g_bfrag + (((size_t)ktg * 256 + (by * 8 + amt)) * 2 + hl) * 32 + ln;
                }
                cpasync16(dst, src);
            }
            asm volatile("cp.async.commit_group;");
            asm volatile("cp.async.wait_group 1;");
        } else {
            asm volatile("cp.async.wait_group 0;");
        }
        __syncthreads();

        int buf = c & 1;
#pragma unroll
        for (int kt = 0; kt < 2; kt++) {
            unsigned bb0 = smem_u32 + XG_BOFF + buf * XG_ABUF
                         + ((kt * 8 + nq * 2) * 2) * 512 + (lane << 4);
            uint4 bh0 = lds128(bb0);
            uint4 bl0 = lds128(bb0 + 512);
            uint4 bh1 = lds128(bb0 + 1024);
            uint4 bl1 = lds128(bb0 + 1536);
#pragma unroll
            for (int mi = 0; mi < 4; mi++) {
                unsigned ab = smem_u32 + buf * XG_ABUF
                            + (((mq * 4 + mi) * 2 + kt) * 2) * 512 + (lane << 4);
                uint4 ah = lds128(ab);
                uint4 al = lds128(ab + 512);
                mma16816(acc[mi][0], ah, bh0.x, bh0.y);
                mma16816(acc[mi][0], ah, bl0.x, bl0.y);
                mma16816(acc[mi][0], al, bh0.x, bh0.y);
                mma16816(acc[mi][1], ah, bh0.z, bh0.w);
                mma16816(acc[mi][1], ah, bl0.z, bl0.w);
                mma16816(acc[mi][1], al, bh0.z, bh0.w);
                mma16816(acc[mi][2], ah, bh1.x, bh1.y);
                mma16816(acc[mi][2], ah, bl1.x, bl1.y);
                mma16816(acc[mi][2], al, bh1.x, bh1.y);
                mma16816(acc[mi][3], ah, bh1.z, bh1.w);
                mma16816(acc[mi][3], ah, bl1.z, bl1.w);
                mma16816(acc[mi][3], al, bh1.z, bh1.w);
            }
        }
        __syncthreads();
    }

    // epilogue: add bias, write g_xp
    const int g = lane >> 2, tq = lane & 3;
#pragma unroll
    for (int mi = 0; mi < 4; mi++) {
        int row = bx * 128 + mq * 64 + mi * 16 + g;
#pragma unroll
        for (int nj = 0; nj < 4; nj++) {
            int col = by * 128 + nq * 32 + nj * 8 + tq * 2;
            float b0 = bias[col], b1 = bias[col + 1];
            float* p0 = g_xp + (size_t)row * GG + col;
            float* p1 = g_xp + (size_t)(row + 8) * GG + col;
            *(float2*)p0 = make_float2(acc[mi][nj][0] + b0, acc[mi][nj][1] + b1);
            *(float2*)p1 = make_float2(acc[mi][nj][2] + b0, acc[mi][nj][3] + b1);
        }
    }
}

// ---------------------------------------------------------------------------
// Persistent recurrence kernel (validated round 3), barrier -> flags.
// ---------------------------------------------------------------------------
#define AOFF 0
#define ABUF_BYTES 32768
#define WOFF 65536
#define DOFF 196608
#define DS_STRIDE 33
#define SMEM_BYTES (DOFF + 64 * DS_STRIDE * 4)

__global__ __launch_bounds__(256, 1) void recurrence_kernel(const float* __restrict__ Wh) {
    extern __shared__ char smem[];
    const int tid  = threadIdx.x;
    const int blk  = blockIdx.x;
    const int warp = tid >> 5, lane = tid & 31;
    const int mw = warp & 3;
    const int np = warp >> 2;
    float* Ds = (float*)(smem + DOFF);
    const unsigned smem_u32 = (unsigned)__cvta_generic_to_shared(smem);

    // one-time: stage Wh slice as B fragments (hi/lo bf16)
    for (int idx = tid; idx < 32 * 1024; idx += 256) {
        int k = idx >> 5, n = idx & 31;
        int gcol = ((n >> 3) << 10) + (blk << 3) + (n & 7);
        float w = Wh[(size_t)k * GG + gcol];
        __nv_bfloat16 hi = __float2bfloat16(w);
        __nv_bfloat16 lo = __float2bfloat16(w - __bfloat162float(hi));
        int kc = k & 15;
        int ln = ((n & 7) << 2) + ((kc & 7) >> 1);
        int by = (((n >> 3) & 1) << 3) + (((kc >> 3) & 1) << 2) + ((kc & 1) << 1);
        int base = WOFF + ((((k >> 4) << 1) + (n >> 4)) << 1) * 512 + (ln << 4) + by;
        *(__nv_bfloat16*)(smem + base)       = hi;
        *(__nv_bfloat16*)(smem + base + 512) = lo;
    }
    __syncthreads();

    const int ub = tid & 63;
    const int up = tid >> 6;
    float creg[2] = {0.f, 0.f};

    for (int t = 0; t < TT; t++) {
        const char* hsrc = (const char*)g_hstage[t & 1];

        {
            const char* src = hsrc + tid * 16;
            unsigned dst = smem_u32 + AOFF + tid * 16;
#pragma unroll
            for (int j = 0; j < 8; j++) cpasync16(dst + j * 4096, src + j * 4096);
            asm volatile("cp.async.commit_group;");
        }

        float acc[2][4] = {{0.f,0.f,0.f,0.f},{0.f,0.f,0.f,0.f}};

        for (int c = 0; c < 8; c++) {
            if (c < 7) {
                const char* src = hsrc + (size_t)(c + 1) * ABUF_BYTES + tid * 16;
                unsigned dst = smem_u32 + AOFF + ((c + 1) & 1) * ABUF_BYTES + tid * 16;
#pragma unroll
                for (int j = 0; j < 8; j++) cpasync16(dst + j * 4096, src + j * 4096);
                asm volatile("cp.async.commit_group;");
                asm volatile("cp.async.wait_group 1;");
            } else {
                asm volatile("cp.async.wait_group 0;");
            }
            __syncthreads();

#pragma unroll
            for (int kt = 0; kt < 8; kt++) {
                unsigned ab = smem_u32 + AOFF + (c & 1) * ABUF_BYTES
                            + ((kt * 4 + mw) * 2) * 512 + (lane << 4);
                uint4 ahi = lds128(ab);
                uint4 alo = lds128(ab + 512);
                int ktg = c * 8 + kt;
                unsigned bb = smem_u32 + WOFF + ((ktg * 2 + np) * 2) * 512 + (lane << 4);
                uint4 bhi = lds128(bb);
                uint4 blo = lds128(bb + 512);
                mma16816(acc[0], ahi, bhi.x, bhi.y);
                mma16816(acc[0], ahi, blo.x, blo.y);
                mma16816(acc[0], alo, bhi.x, bhi.y);
                mma16816(acc[1], ahi, bhi.z, bhi.w);
                mma16816(acc[1], ahi, blo.z, blo.w);
                mma16816(acc[1], alo, bhi.z, bhi.w);
            }
            __syncthreads();
        }

        {
            int g = lane >> 2, tq = lane & 3;
            int row0 = (mw << 4) + g;
#pragma unroll
            for (int nt = 0; nt < 2; nt++) {
                int cb = (np << 4) + (nt << 3) + (tq << 1);
                Ds[row0 * DS_STRIDE + cb]            = acc[nt][0];
                Ds[row0 * DS_STRIDE + cb + 1]        = acc[nt][1];
                Ds[(row0 + 8) * DS_STRIDE + cb]      = acc[nt][2];
                Ds[(row0 + 8) * DS_STRIDE + cb + 1]  = acc[nt][3];
            }
        }
        __syncthreads();

        {
            const float* xp = g_xp + ((size_t)t * BB + ub) * GG;
            char* hdst = (char*)g_hstage[(t + 1) & 1];
#pragma unroll
            for (int pi = 0; pi < 2; pi++) {
                int p = up + pi * 4;
                int unit = (blk << 3) + p;
                float di = Ds[ub * DS_STRIDE + p];
                float df = Ds[ub * DS_STRIDE + 8 + p];
                float dg = Ds[ub * DS_STRIDE + 16 + p];
                float dz = Ds[ub * DS_STRIDE + 24 + p];
                float gi = xp[unit]          + di;
                float gf = xp[HH + unit]     + df;
                float gg = xp[2 * HH + unit] + dg;
                float go = xp[3 * HH + unit] + dz;
                float si = 1.f / (1.f + expf(-gi));
                float sf = 1.f / (1.f + expf(-gf));
                float tg = tanhf(gg);
                float so = 1.f / (1.f + expf(-go));
                float cn = fmaf(sf, creg[pi], si * tg);
                creg[pi] = cn;
                float hn = so * tanhf(cn);

                int r = ub & 15, mt = ub >> 4;
                int kc = unit & 15, ktile = unit >> 4;
                int ln  = ((r & 7) << 2) + ((kc & 7) >> 1);
                int reg = (((kc >> 3) & 1) << 1) + ((r >> 3) & 1);
                int off = (((ktile << 2) + mt) << 1) * 512 + (ln << 4)
                        + (reg << 2) + ((kc & 1) << 1);
                __nv_bfloat16 hi = __float2bfloat16(hn);
                __nv_bfloat16 lo = __float2bfloat16(hn - __bfloat162float(hi));
                *(__nv_bfloat16*)(hdst + off)       = hi;
                *(__nv_bfloat16*)(hdst + off + 512) = lo;
                if (t == TT - 1) g_h[ub * HH + unit] = hn;
            }
        }

        // -------- distributed-flag grid barrier --------
        __threadfence();
        __syncthreads();
        if (tid < 32) {
            if (tid == 0) *(volatile unsigned*)&g_flags[blk] = (unsigned)(t + 1);
            unsigned tgt = (unsigned)(t + 1);
#pragma unroll
            for (int i = 0; i < 4; i++) {
                while (*(volatile unsigned*)&g_flags[lane + i * 32] < tgt) { }
            }
        }
        __syncthreads();
    }
}

// ---------------------------------------------------------------------------
// classifier: 64 blocks (one per batch), 128 threads, float4 Wd rows.
// ---------------------------------------------------------------------------
__global__ __launch_bounds__(128) void classifier_kernel(
        const float* __restrict__ Wd, const float* __restrict__ bd,
        float* __restrict__ out) {
    __shared__ float4 red[4];
    int b = blockIdx.x, tid = threadIdx.x;
    int lane = tid & 31, warp = tid >> 5;
    float4 a = make_float4(0.f, 0.f, 0.f, 0.f);
    for (int k = tid; k < HH; k += 128) {
        float h = g_h[b * HH + k];
        float4 w = *(const float4*)(Wd + k * CC);
        a.x = fmaf(h, w.x, a.x); a.y = fmaf(h, w.y, a.y);
        a.z = fmaf(h, w.z, a.z); a.w = fmaf(h, w.w, a.w);
    }
#pragma unroll
    for (int s = 16; s > 0; s >>= 1) {
        a.x += __shfl_xor_sync(0xffffffffu, a.x, s);
        a.y += __shfl_xor_sync(0xffffffffu, a.y, s);
        a.z += __shfl_xor_sync(0xffffffffu, a.z, s);
        a.w += __shfl_xor_sync(0xffffffffu, a.w, s);
    }
    if (lane == 0) red[warp] = a;
    __syncthreads();
    if (tid == 0) {
        float4 s = red[0];
        s.x += red[1].x + red[2].x + red[3].x;
        s.y += red[1].y + red[2].y + red[3].y;
        s.z += red[1].z + red[2].z + red[3].z;
        s.w += red[1].w + red[2].w + red[3].w;
        out[b * CC + 0] = s.x + bd[0];
        out[b * CC + 1] = s.y + bd[1];
        out[b * CC + 2] = s.z + bd[2];
        out[b * CC + 3] = s.w + bd[3];
    }
}

// ---------------------------------------------------------------------------
// launch: 6 graph nodes
// ---------------------------------------------------------------------------
extern "C" void kernel_launch(void* const* d_in, const int* in_sizes, int n_in,
                              void* d_out, int out_size) {
    const int*   tokens = (const int*)d_in[0];
    const float* emb    = (const float*)d_in[1];
    const float* Wi     = (const float*)d_in[2];
    const float* Wh     = (const float*)d_in[3];
    const float* bias   = (const float*)d_in[4];
    const float* Wd     = (const float*)d_in[5];
    const float* bd     = (const float*)d_in[6];
    float* out = (float*)d_out;

    cudaFuncSetAttribute(recurrence_kernel,
                         cudaFuncAttributeMaxDynamicSharedMemorySize, SMEM_BYTES);
    cudaFuncSetAttribute(xgemm_kernel,
                         cudaFuncAttributeMaxDynamicSharedMemorySize, XG_SMEM);

    init_kernel<<<64, 256>>>();
    conv_a_kernel<<<2048 * 32 / 8, 256>>>(tokens, emb);
    conv_b_kernel<<<32 * 256 / 8, 256>>>(Wi);

    dim3 xg(256, 32);
    xgemm_kernel<<<xg, 256, XG_SMEM>>>(bias);

    recurrence_kernel<<<NBLK, 256, SMEM_BYTES>>>(Wh);

    classifier_kernel<<<BB, 128>>>(Wd, bd, out);
}

// round 5
// speedup vs baseline: 1.2118x; 1.2118x over previous
#include <cuda_runtime.h>
#include <cuda_bf16.h>
#include <math.h>

#define BB 64
#define TT 512
#define EE 512
#define HH 1024
#define GG 4096   // 4*H
#define CC 4
#define NBLK 128  // persistent recurrence blocks

// ---------------------------------------------------------------------------
// Global scratch (static device arrays — no runtime allocation)
// ---------------------------------------------------------------------------
__device__ float g_xp[(size_t)TT * BB * GG];          // [T][B][4H] input projections
__device__ float g_h[BB * HH];                        // final hidden state
// h staged as bf16 hi/lo MMA A-fragments: [buf][ktile 64][mtile 4][hl 2][lane 32] x 16B
__device__ uint4 g_hstage[2][64 * 4 * 2 * 32];
__device__ unsigned g_bar;                            // monotonic barrier counter

// xproj operands pre-converted to MMA fragment layout (bf16 hi/lo):
// A: [mtile 2048][ktile 32][hl 2][lane 32] x 16B   (rows m = t*64+b)
__device__ uint4 g_afrag[(size_t)2048 * 32 * 2 * 32];   // 64 MB
// B: [ktile 32][ntile16 256][hl 2][lane 32] x 16B
__device__ uint4 g_bfrag[(size_t)32 * 256 * 2 * 32];    // 8 MB

// ---------------------------------------------------------------------------
// helpers
// ---------------------------------------------------------------------------
__device__ __forceinline__ void cpasync16(unsigned dst, const void* src) {
    asm volatile("cp.async.cg.shared.global [%0], [%1], 16;" :: "r"(dst), "l"(src));
}
__device__ __forceinline__ uint4 lds128(unsigned addr) {
    uint4 v;
    asm volatile("ld.shared.v4.u32 {%0,%1,%2,%3}, [%4];"
                 : "=r"(v.x), "=r"(v.y), "=r"(v.z), "=r"(v.w) : "r"(addr));
    return v;
}
__device__ __forceinline__ void mma16816(float* d, const uint4& a, unsigned b0, unsigned b1) {
    asm volatile("mma.sync.aligned.m16n8k16.row.col.f32.bf16.bf16.f32 "
                 "{%0,%1,%2,%3}, {%4,%5,%6,%7}, {%8,%9}, {%0,%1,%2,%3};"
                 : "+f"(d[0]), "+f"(d[1]), "+f"(d[2]), "+f"(d[3])
                 : "r"(a.x), "r"(a.y), "r"(a.z), "r"(a.w), "r"(b0), "r"(b1));
}
__device__ __forceinline__ unsigned pack_hi(float x0, float x1) {
    unsigned h0 = (unsigned)__bfloat16_as_ushort(__float2bfloat16(x0));
    unsigned h1 = (unsigned)__bfloat16_as_ushort(__float2bfloat16(x1));
    return h0 | (h1 << 16);
}
__device__ __forceinline__ unsigned pack_lo(float x0, float x1) {
    float r0 = x0 - __bfloat162float(__float2bfloat16(x0));
    float r1 = x1 - __bfloat162float(__float2bfloat16(x1));
    unsigned h0 = (unsigned)__bfloat16_as_ushort(__float2bfloat16(r0));
    unsigned h1 = (unsigned)__bfloat16_as_ushort(__float2bfloat16(r1));
    return h0 | (h1 << 16);
}

// ---------------------------------------------------------------------------
// init: zero barrier counter + h(-1) staging buffer 0
// ---------------------------------------------------------------------------
__global__ void init_kernel() {
    int i = blockIdx.x * blockDim.x + threadIdx.x;
    if (i == 0) g_bar = 0u;
    if (i < 64 * 4 * 2 * 32) g_hstage[0][i] = make_uint4(0u, 0u, 0u, 0u);
}

// ---------------------------------------------------------------------------
// conv_a: gather emb rows, convert to bf16 hi/lo A-fragment layout.
// ---------------------------------------------------------------------------
__global__ __launch_bounds__(256) void conv_a_kernel(
        const int* __restrict__ tokens, const float* __restrict__ emb) {
    int gw = (blockIdx.x * 256 + threadIdx.x) >> 5;
    int lane = threadIdx.x & 31;
    int mt = gw >> 5;          // 0..2047
    int kt = gw & 31;          // 0..31
    int t_ = mt >> 2;
    int b0_ = ((mt & 3) << 4) + (lane >> 2);
    int b1_ = b0_ + 8;
    const float* er0 = emb + (size_t)tokens[b0_ * TT + t_] * EE + kt * 16;
    const float* er1 = emb + (size_t)tokens[b1_ * TT + t_] * EE + kt * 16;

    unsigned hi[4], lo[4];
#pragma unroll
    for (int r2 = 0; r2 < 4; r2++) {
        const float* er = (r2 & 1) ? er1 : er0;
        int kc0 = ((lane & 3) << 1) + ((r2 >> 1) << 3);
        float x0 = er[kc0], x1 = er[kc0 + 1];
        hi[r2] = pack_hi(x0, x1);
        lo[r2] = pack_lo(x0, x1);
    }
    size_t base = ((size_t)(mt * 32 + kt) * 2) * 32 + lane;
    g_afrag[base]      = make_uint4(hi[0], hi[1], hi[2], hi[3]);
    g_afrag[base + 32] = make_uint4(lo[0], lo[1], lo[2], lo[3]);
}

// ---------------------------------------------------------------------------
// conv_b: Wi -> bf16 hi/lo B-fragment layout.
// ---------------------------------------------------------------------------
__global__ __launch_bounds__(256) void conv_b_kernel(const float* __restrict__ Wi) {
    int gw = (blockIdx.x * 256 + threadIdx.x) >> 5;
    int lane = threadIdx.x & 31;
    int kt = gw >> 8;          // 0..31
    int nt = gw & 255;         // 0..255

    unsigned hi[4], lo[4];
#pragma unroll
    for (int w = 0; w < 4; w++) {
        int n  = ((w >> 1) << 3) + (lane >> 2);
        int kc0 = ((lane & 3) << 1) + ((w & 1) << 3);
        const float* p = Wi + (size_t)(kt * 16 + kc0) * GG + nt * 16 + n;
        float x0 = p[0], x1 = p[GG];
        hi[w] = pack_hi(x0, x1);
        lo[w] = pack_lo(x0, x1);
    }
    size_t base = ((size_t)(kt * 256 + nt) * 2) * 32 + lane;
    g_bfrag[base]      = make_uint4(hi[0], hi[1], hi[2], hi[3]);
    g_bfrag[base + 32] = make_uint4(lo[0], lo[1], lo[2], lo[3]);
}

// ---------------------------------------------------------------------------
// xgemm: XP = X @ Wi + bias via bf16 split-3 MMA. 128x128 tile.
// ---------------------------------------------------------------------------
#define XG_ABUF 16384
#define XG_BOFF 32768
#define XG_SMEM 65536

__global__ __launch_bounds__(256) void xgemm_kernel(const float* __restrict__ bias) {
    extern __shared__ char smem[];
    const unsigned smem_u32 = (unsigned)__cvta_generic_to_shared(smem);
    const int tid = threadIdx.x;
    const int warp = tid >> 5, lane = tid & 31;
    const int mq = warp & 1;
    const int nq = warp >> 1;
    const int bx = blockIdx.x, by = blockIdx.y;

    const bool isA = tid < 128;
    const int amt = (tid & 127) >> 4;
    const int sub = tid & 15;

    float acc[4][4][4];
#pragma unroll
    for (int i = 0; i < 4; i++)
#pragma unroll
        for (int j = 0; j < 4; j++)
#pragma unroll
            for (int q = 0; q < 4; q++) acc[i][j][q] = 0.f;

#pragma unroll
    for (int j = 0; j < 8; j++) {
        int q = sub * 8 + j;
        int kt = q >> 6, hl = (q >> 5) & 1, ln = q & 31;
        unsigned dst; const uint4* src;
        if (isA) {
            dst = smem_u32 + ((amt * 2 + kt) * 2 + hl) * 512 + ln * 16;
            src = g_afrag + (((size_t)(bx * 8 + amt) * 32 + kt) * 2 + hl) * 32 + ln;
        } else {
            dst = smem_u32 + XG_BOFF + ((kt * 8 + amt) * 2 + hl) * 512 + ln * 16;
            src = g_bfrag + (((size_t)kt * 256 + (by * 8 + amt)) * 2 + hl) * 32 + ln;
        }
        cpasync16(dst, src);
    }
    asm volatile("cp.async.commit_group;");

    for (int c = 0; c < 16; c++) {
        if (c < 15) {
            int buf = (c + 1) & 1;
#pragma unroll
            for (int j = 0; j < 8; j++) {
                int q = sub * 8 + j;
                int kt = q >> 6, hl = (q >> 5) & 1, ln = q & 31;
                int ktg = (c + 1) * 2 + kt;
                unsigned dst; const uint4* src;
                if (isA) {
                    dst = smem_u32 + buf * XG_ABUF + ((amt * 2 + kt) * 2 + hl) * 512 + ln * 16;
                    src = g_afrag + (((size_t)(bx * 8 + amt) * 32 + ktg) * 2 + hl) * 32 + ln;
                } else {
                    dst = smem_u32 + XG_BOFF + buf * XG_ABUF + ((kt * 8 + amt) * 2 + hl) * 512 + ln * 16;
                    src = g_bfrag + (((size_t)ktg * 256 + (by * 8 + amt)) * 2 + hl) * 32 + ln;
                }
                cpasync16(dst, src);
            }
            asm volatile("cp.async.commit_group;");
            asm volatile("cp.async.wait_group 1;");
        } else {
            asm volatile("cp.async.wait_group 0;");
        }
        __syncthreads();

        int buf = c & 1;
#pragma unroll
        for (int kt = 0; kt < 2; kt++) {
            unsigned bb0 = smem_u32 + XG_BOFF + buf * XG_ABUF
                         + ((kt * 8 + nq * 2) * 2) * 512 + (lane << 4);
            uint4 bh0 = lds128(bb0);
            uint4 bl0 = lds128(bb0 + 512);
            uint4 bh1 = lds128(bb0 + 1024);
            uint4 bl1 = lds128(bb0 + 1536);
#pragma unroll
            for (int mi = 0; mi < 4; mi++) {
                unsigned ab = smem_u32 + buf * XG_ABUF
                            + (((mq * 4 + mi) * 2 + kt) * 2) * 512 + (lane << 4);
                uint4 ah = lds128(ab);
                uint4 al = lds128(ab + 512);
                mma16816(acc[mi][0], ah, bh0.x, bh0.y);
                mma16816(acc[mi][0], ah, bl0.x, bl0.y);
                mma16816(acc[mi][0], al, bh0.x, bh0.y);
                mma16816(acc[mi][1], ah, bh0.z, bh0.w);
                mma16816(acc[mi][1], ah, bl0.z, bl0.w);
                mma16816(acc[mi][1], al, bh0.z, bh0.w);
                mma16816(acc[mi][2], ah, bh1.x, bh1.y);
                mma16816(acc[mi][2], ah, bl1.x, bl1.y);
                mma16816(acc[mi][2], al, bh1.x, bh1.y);
                mma16816(acc[mi][3], ah, bh1.z, bh1.w);
                mma16816(acc[mi][3], ah, bl1.z, bl1.w);
                mma16816(acc[mi][3], al, bh1.z, bh1.w);
            }
        }
        __syncthreads();
    }

    const int g = lane >> 2, tq = lane & 3;
#pragma unroll
    for (int mi = 0; mi < 4; mi++) {
        int row = bx * 128 + mq * 64 + mi * 16 + g;
#pragma unroll
        for (int nj = 0; nj < 4; nj++) {
            int col = by * 128 + nq * 32 + nj * 8 + tq * 2;
            float b0 = bias[col], b1 = bias[col + 1];
            float* p0 = g_xp + (size_t)row * GG + col;
            float* p1 = g_xp + (size_t)(row + 8) * GG + col;
            *(float2*)p0 = make_float2(acc[mi][nj][0] + b0, acc[mi][nj][1] + b1);
            *(float2*)p1 = make_float2(acc[mi][nj][2] + b0, acc[mi][nj][3] + b1);
        }
    }
}

// ---------------------------------------------------------------------------
// Persistent recurrence kernel (validated round 3, atomic barrier).
// ---------------------------------------------------------------------------
#define AOFF 0
#define ABUF_BYTES 32768
#define WOFF 65536
#define DOFF 196608
#define DS_STRIDE 33
#define SMEM_BYTES (DOFF + 64 * DS_STRIDE * 4)

__global__ __launch_bounds__(256, 1) void recurrence_kernel(const float* __restrict__ Wh) {
    extern __shared__ char smem[];
    const int tid  = threadIdx.x;
    const int blk  = blockIdx.x;
    const int warp = tid >> 5, lane = tid & 31;
    const int mw = warp & 3;
    const int np = warp >> 2;
    float* Ds = (float*)(smem + DOFF);
    const unsigned smem_u32 = (unsigned)__cvta_generic_to_shared(smem);

    // one-time: stage Wh slice as B fragments (hi/lo bf16)
    for (int idx = tid; idx < 32 * 1024; idx += 256) {
        int k = idx >> 5, n = idx & 31;
        int gcol = ((n >> 3) << 10) + (blk << 3) + (n & 7);
        float w = Wh[(size_t)k * GG + gcol];
        __nv_bfloat16 hi = __float2bfloat16(w);
        __nv_bfloat16 lo = __float2bfloat16(w - __bfloat162float(hi));
        int kc = k & 15;
        int ln = ((n & 7) << 2) + ((kc & 7) >> 1);
        int by = (((n >> 3) & 1) << 3) + (((kc >> 3) & 1) << 2) + ((kc & 1) << 1);
        int base = WOFF + ((((k >> 4) << 1) + (n >> 4)) << 1) * 512 + (ln << 4) + by;
        *(__nv_bfloat16*)(smem + base)       = hi;
        *(__nv_bfloat16*)(smem + base + 512) = lo;
    }
    __syncthreads();

    const int ub = tid & 63;
    const int up = tid >> 6;
    float creg[2] = {0.f, 0.f};

    for (int t = 0; t < TT; t++) {
        const char* hsrc = (const char*)g_hstage[t & 1];

        {
            const char* src = hsrc + tid * 16;
            unsigned dst = smem_u32 + AOFF + tid * 16;
#pragma unroll
            for (int j = 0; j < 8; j++) cpasync16(dst + j * 4096, src + j * 4096);
            asm volatile("cp.async.commit_group;");
        }

        float acc[2][4] = {{0.f,0.f,0.f,0.f},{0.f,0.f,0.f,0.f}};

        for (int c = 0; c < 8; c++) {
            if (c < 7) {
                const char* src = hsrc + (size_t)(c + 1) * ABUF_BYTES + tid * 16;
                unsigned dst = smem_u32 + AOFF + ((c + 1) & 1) * ABUF_BYTES + tid * 16;
#pragma unroll
                for (int j = 0; j < 8; j++) cpasync16(dst + j * 4096, src + j * 4096);
                asm volatile("cp.async.commit_group;");
                asm volatile("cp.async.wait_group 1;");
            } else {
                asm volatile("cp.async.wait_group 0;");
            }
            __syncthreads();

#pragma unroll
            for (int kt = 0; kt < 8; kt++) {
                unsigned ab = smem_u32 + AOFF + (c & 1) * ABUF_BYTES
                            + ((kt * 4 + mw) * 2) * 512 + (lane << 4);
                uint4 ahi = lds128(ab);
                uint4 alo = lds128(ab + 512);
                int ktg = c * 8 + kt;
                unsigned bb = smem_u32 + WOFF + ((ktg * 2 + np) * 2) * 512 + (lane << 4);
                uint4 bhi = lds128(bb);
                uint4 blo = lds128(bb + 512);
                mma16816(acc[0], ahi, bhi.x, bhi.y);
                mma16816(acc[0], ahi, blo.x, blo.y);
                mma16816(acc[0], alo, bhi.x, bhi.y);
                mma16816(acc[1], ahi, bhi.z, bhi.w);
                mma16816(acc[1], ahi, blo.z, blo.w);
                mma16816(acc[1], alo, bhi.z, bhi.w);
            }
            __syncthreads();
        }

        {
            int g = lane >> 2, tq = lane & 3;
            int row0 = (mw << 4) + g;
#pragma unroll
            for (int nt = 0; nt < 2; nt++) {
                int cb = (np << 4) + (nt << 3) + (tq << 1);
                Ds[row0 * DS_STRIDE + cb]            = acc[nt][0];
                Ds[row0 * DS_STRIDE + cb + 1]        = acc[nt][1];
                Ds[(row0 + 8) * DS_STRIDE + cb]      = acc[nt][2];
                Ds[(row0 + 8) * DS_STRIDE + cb + 1]  = acc[nt][3];
            }
        }
        __syncthreads();

        {
            const float* xp = g_xp + ((size_t)t * BB + ub) * GG;
            char* hdst = (char*)g_hstage[(t + 1) & 1];
#pragma unroll
            for (int pi = 0; pi < 2; pi++) {
                int p = up + pi * 4;
                int unit = (blk << 3) + p;
                float di = Ds[ub * DS_STRIDE + p];
                float df = Ds[ub * DS_STRIDE + 8 + p];
                float dg = Ds[ub * DS_STRIDE + 16 + p];
                float dz = Ds[ub * DS_STRIDE + 24 + p];
                float gi = xp[unit]          + di;
                float gf = xp[HH + unit]     + df;
                float gg = xp[2 * HH + unit] + dg;
                float go = xp[3 * HH + unit] + dz;
                float si = 1.f / (1.f + expf(-gi));
                float sf = 1.f / (1.f + expf(-gf));
                float tg = tanhf(gg);
                float so = 1.f / (1.f + expf(-go));
                float cn = fmaf(sf, creg[pi], si * tg);
                creg[pi] = cn;
                float hn = so * tanhf(cn);

                int r = ub & 15, mt = ub >> 4;
                int kc = unit & 15, ktile = unit >> 4;
                int ln  = ((r & 7) << 2) + ((kc & 7) >> 1);
                int reg = (((kc >> 3) & 1) << 1) + ((r >> 3) & 1);
                int off = (((ktile << 2) + mt) << 1) * 512 + (ln << 4)
                        + (reg << 2) + ((kc & 1) << 1);
                __nv_bfloat16 hi = __float2bfloat16(hn);
                __nv_bfloat16 lo = __float2bfloat16(hn - __bfloat162float(hi));
                *(__nv_bfloat16*)(hdst + off)       = hi;
                *(__nv_bfloat16*)(hdst + off + 512) = lo;
                if (t == TT - 1) g_h[ub * HH + unit] = hn;
            }
        }

        // -------- atomic monotonic-counter grid barrier (validated R3) --------
        __threadfence();
        __syncthreads();
        if (tid == 0) {
            atomicAdd(&g_bar, 1u);
            unsigned tgt = (unsigned)(NBLK * (t + 1));
            while (*((volatile unsigned*)&g_bar) < tgt) { }
        }
        __syncthreads();
    }
}

// ---------------------------------------------------------------------------
// classifier: 64 blocks (one per batch), 128 threads, float4 Wd rows.
// ---------------------------------------------------------------------------
__global__ __launch_bounds__(128) void classifier_kernel(
        const float* __restrict__ Wd, const float* __restrict__ bd,
        float* __restrict__ out) {
    __shared__ float4 red[4];
    int b = blockIdx.x, tid = threadIdx.x;
    int lane = tid & 31, warp = tid >> 5;
    float4 a = make_float4(0.f, 0.f, 0.f, 0.f);
    for (int k = tid; k < HH; k += 128) {
        float h = g_h[b * HH + k];
        float4 w = *(const float4*)(Wd + k * CC);
        a.x = fmaf(h, w.x, a.x); a.y = fmaf(h, w.y, a.y);
        a.z = fmaf(h, w.z, a.z); a.w = fmaf(h, w.w, a.w);
    }
#pragma unroll
    for (int s = 16; s > 0; s >>= 1) {
        a.x += __shfl_xor_sync(0xffffffffu, a.x, s);
        a.y += __shfl_xor_sync(0xffffffffu, a.y, s);
        a.z += __shfl_xor_sync(0xffffffffu, a.z, s);
        a.w += __shfl_xor_sync(0xffffffffu, a.w, s);
    }
    if (lane == 0) red[warp] = a;
    __syncthreads();
    if (tid == 0) {
        float4 s = red[0];
        s.x += red[1].x + red[2].x + red[3].x;
        s.y += red[1].y + red[2].y + red[3].y;
        s.z += red[1].z + red[2].z + red[3].z;
        s.w += red[1].w + red[2].w + red[3].w;
        out[b * CC + 0] = s.x + bd[0];
        out[b * CC + 1] = s.y + bd[1];
        out[b * CC + 2] = s.z + bd[2];
        out[b * CC + 3] = s.w + bd[3];
    }
}

// ---------------------------------------------------------------------------
// launch: 6 graph nodes
// ---------------------------------------------------------------------------
extern "C" void kernel_launch(void* const* d_in, const int* in_sizes, int n_in,
                              void* d_out, int out_size) {
    const int*   tokens = (const int*)d_in[0];
    const float* emb    = (const float*)d_in[1];
    const float* Wi     = (const float*)d_in[2];
    const float* Wh     = (const float*)d_in[3];
    const float* bias   = (const float*)d_in[4];
    const float* Wd     = (const float*)d_in[5];
    const float* bd     = (const float*)d_in[6];
    float* out = (float*)d_out;

    cudaFuncSetAttribute(recurrence_kernel,
                         cudaFuncAttributeMaxDynamicSharedMemorySize, SMEM_BYTES);
    cudaFuncSetAttribute(xgemm_kernel,
                         cudaFuncAttributeMaxDynamicSharedMemorySize, XG_SMEM);

    init_kernel<<<64, 256>>>();
    conv_a_kernel<<<2048 * 32 / 8, 256>>>(tokens, emb);
    conv_b_kernel<<<32 * 256 / 8, 256>>>(Wi);

    dim3 xg(256, 32);
    xgemm_kernel<<<xg, 256, XG_SMEM>>>(bias);

    recurrence_kernel<<<NBLK, 256, SMEM_BYTES>>>(Wh);

    classifier_kernel<<<BB, 128>>>(Wd, bd, out);
}

// round 6
// speedup vs baseline: 1.2126x; 1.0006x over previous
#include <cuda_runtime.h>
#include <cuda_bf16.h>
#include <math.h>

#define BB 64
#define TT 512
#define EE 512
#define HH 1024
#define GG 4096   // 4*H
#define CC 4
#define NBLK 128  // persistent recurrence blocks

// ---------------------------------------------------------------------------
// Global scratch (static device arrays — no runtime allocation)
// ---------------------------------------------------------------------------
__device__ float g_xp[(size_t)TT * BB * GG];          // [T][B][4H] input projections
__device__ float g_h[BB * HH];                        // final hidden state
// h staged as bf16 hi/lo MMA A-fragments: [buf][ktile 64][mtile 4][hl 2][lane 32] x 16B
__device__ uint4 g_hstage[2][64 * 4 * 2 * 32];
__device__ unsigned g_bar;                            // global barrier counter
__device__ unsigned g_grp[16 * 32];                   // 16 group counters, 128B apart

// xproj operands pre-converted to MMA fragment layout (bf16 hi/lo)
__device__ uint4 g_afrag[(size_t)2048 * 32 * 2 * 32];   // 64 MB
__device__ uint4 g_bfrag[(size_t)32 * 256 * 2 * 32];    // 8 MB

// ---------------------------------------------------------------------------
// helpers
// ---------------------------------------------------------------------------
__device__ __forceinline__ void cpasync16(unsigned dst, const void* src) {
    asm volatile("cp.async.cg.shared.global [%0], [%1], 16;" :: "r"(dst), "l"(src));
}
__device__ __forceinline__ uint4 lds128(unsigned addr) {
    uint4 v;
    asm volatile("ld.shared.v4.u32 {%0,%1,%2,%3}, [%4];"
                 : "=r"(v.x), "=r"(v.y), "=r"(v.z), "=r"(v.w) : "r"(addr));
    return v;
}
__device__ __forceinline__ void mma16816(float* d, const uint4& a, unsigned b0, unsigned b1) {
    asm volatile("mma.sync.aligned.m16n8k16.row.col.f32.bf16.bf16.f32 "
                 "{%0,%1,%2,%3}, {%4,%5,%6,%7}, {%8,%9}, {%0,%1,%2,%3};"
                 : "+f"(d[0]), "+f"(d[1]), "+f"(d[2]), "+f"(d[3])
                 : "r"(a.x), "r"(a.y), "r"(a.z), "r"(a.w), "r"(b0), "r"(b1));
}
__device__ __forceinline__ unsigned pack_hi(float x0, float x1) {
    unsigned h0 = (unsigned)__bfloat16_as_ushort(__float2bfloat16(x0));
    unsigned h1 = (unsigned)__bfloat16_as_ushort(__float2bfloat16(x1));
    return h0 | (h1 << 16);
}
__device__ __forceinline__ unsigned pack_lo(float x0, float x1) {
    float r0 = x0 - __bfloat162float(__float2bfloat16(x0));
    float r1 = x1 - __bfloat162float(__float2bfloat16(x1));
    unsigned h0 = (unsigned)__bfloat16_as_ushort(__float2bfloat16(r0));
    unsigned h1 = (unsigned)__bfloat16_as_ushort(__float2bfloat16(r1));
    return h0 | (h1 << 16);
}

// ---------------------------------------------------------------------------
// init
// ---------------------------------------------------------------------------
__global__ void init_kernel() {
    int i = blockIdx.x * blockDim.x + threadIdx.x;
    if (i == 0) g_bar = 0u;
    if (i < 16 * 32) g_grp[i] = 0u;
    if (i < 64 * 4 * 2 * 32) g_hstage[0][i] = make_uint4(0u, 0u, 0u, 0u);
}

// ---------------------------------------------------------------------------
// conv_a: gather emb rows, convert to bf16 hi/lo A-fragment layout.
// ---------------------------------------------------------------------------
__global__ __launch_bounds__(256) void conv_a_kernel(
        const int* __restrict__ tokens, const float* __restrict__ emb) {
    int gw = (blockIdx.x * 256 + threadIdx.x) >> 5;
    int lane = threadIdx.x & 31;
    int mt = gw >> 5;          // 0..2047
    int kt = gw & 31;          // 0..31
    int t_ = mt >> 2;
    int b0_ = ((mt & 3) << 4) + (lane >> 2);
    int b1_ = b0_ + 8;
    const float* er0 = emb + (size_t)tokens[b0_ * TT + t_] * EE + kt * 16;
    const float* er1 = emb + (size_t)tokens[b1_ * TT + t_] * EE + kt * 16;

    unsigned hi[4], lo[4];
#pragma unroll
    for (int r2 = 0; r2 < 4; r2++) {
        const float* er = (r2 & 1) ? er1 : er0;
        int kc0 = ((lane & 3) << 1) + ((r2 >> 1) << 3);
        float x0 = er[kc0], x1 = er[kc0 + 1];
        hi[r2] = pack_hi(x0, x1);
        lo[r2] = pack_lo(x0, x1);
    }
    size_t base = ((size_t)(mt * 32 + kt) * 2) * 32 + lane;
    g_afrag[base]      = make_uint4(hi[0], hi[1], hi[2], hi[3]);
    g_afrag[base + 32] = make_uint4(lo[0], lo[1], lo[2], lo[3]);
}

// ---------------------------------------------------------------------------
// conv_b: Wi -> bf16 hi/lo B-fragment layout.
// ---------------------------------------------------------------------------
__global__ __launch_bounds__(256) void conv_b_kernel(const float* __restrict__ Wi) {
    int gw = (blockIdx.x * 256 + threadIdx.x) >> 5;
    int lane = threadIdx.x & 31;
    int kt = gw >> 8;          // 0..31
    int nt = gw & 255;         // 0..255

    unsigned hi[4], lo[4];
#pragma unroll
    for (int w = 0; w < 4; w++) {
        int n  = ((w >> 1) << 3) + (lane >> 2);
        int kc0 = ((lane & 3) << 1) + ((w & 1) << 3);
        const float* p = Wi + (size_t)(kt * 16 + kc0) * GG + nt * 16 + n;
        float x0 = p[0], x1 = p[GG];
        hi[w] = pack_hi(x0, x1);
        lo[w] = pack_lo(x0, x1);
    }
    size_t base = ((size_t)(kt * 256 + nt) * 2) * 32 + lane;
    g_bfrag[base]      = make_uint4(hi[0], hi[1], hi[2], hi[3]);
    g_bfrag[base + 32] = make_uint4(lo[0], lo[1], lo[2], lo[3]);
}

// ---------------------------------------------------------------------------
// xgemm: XP = X @ Wi + bias via bf16 split-3 MMA. 128x128 tile. (validated)
// ---------------------------------------------------------------------------
#define XG_ABUF 16384
#define XG_BOFF 32768
#define XG_SMEM 65536

__global__ __launch_bounds__(256) void xgemm_kernel(const float* __restrict__ bias) {
    extern __shared__ char smem[];
    const unsigned smem_u32 = (unsigned)__cvta_generic_to_shared(smem);
    const int tid = threadIdx.x;
    const int warp = tid >> 5, lane = tid & 31;
    const int mq = warp & 1;
    const int nq = warp >> 1;
    const int bx = blockIdx.x, by = blockIdx.y;

    const bool isA = tid < 128;
    const int amt = (tid & 127) >> 4;
    const int sub = tid & 15;

    float acc[4][4][4];
#pragma unroll
    for (int i = 0; i < 4; i++)
#pragma unroll
        for (int j = 0; j < 4; j++)
#pragma unroll
            for (int q = 0; q < 4; q++) acc[i][j][q] = 0.f;

#pragma unroll
    for (int j = 0; j < 8; j++) {
        int q = sub * 8 + j;
        int kt = q >> 6, hl = (q >> 5) & 1, ln = q & 31;
        unsigned dst; const uint4* src;
        if (isA) {
            dst = smem_u32 + ((amt * 2 + kt) * 2 + hl) * 512 + ln * 16;
            src = g_afrag + (((size_t)(bx * 8 + amt) * 32 + kt) * 2 + hl) * 32 + ln;
        } else {
            dst = smem_u32 + XG_BOFF + ((kt * 8 + amt) * 2 + hl) * 512 + ln * 16;
            src = g_bfrag + (((size_t)kt * 256 + (by * 8 + amt)) * 2 + hl) * 32 + ln;
        }
        cpasync16(dst, src);
    }
    asm volatile("cp.async.commit_group;");

    for (int c = 0; c < 16; c++) {
        if (c < 15) {
            int buf = (c + 1) & 1;
#pragma unroll
            for (int j = 0; j < 8; j++) {
                int q = sub * 8 + j;
                int kt = q >> 6, hl = (q >> 5) & 1, ln = q & 31;
                int ktg = (c + 1) * 2 + kt;
                unsigned dst; const uint4* src;
                if (isA) {
                    dst = smem_u32 + buf * XG_ABUF + ((amt * 2 + kt) * 2 + hl) * 512 + ln * 16;
                    src = g_afrag + (((size_t)(bx * 8 + amt) * 32 + ktg) * 2 + hl) * 32 + ln;
                } else {
                    dst = smem_u32 + XG_BOFF + buf * XG_ABUF + ((kt * 8 + amt) * 2 + hl) * 512 + ln * 16;
                    src = g_bfrag + (((size_t)ktg * 256 + (by * 8 + amt)) * 2 + hl) * 32 + ln;
                }
                cpasync16(dst, src);
            }
            asm volatile("cp.async.commit_group;");
            asm volatile("cp.async.wait_group 1;");
        } else {
            asm volatile("cp.async.wait_group 0;");
        }
        __syncthreads();

        int buf = c & 1;
#pragma unroll
        for (int kt = 0; kt < 2; kt++) {
            unsigned bb0 = smem_u32 + XG_BOFF + buf * XG_ABUF
                         + ((kt * 8 + nq * 2) * 2) * 512 + (lane << 4);
            uint4 bh0 = lds128(bb0);
            uint4 bl0 = lds128(bb0 + 512);
            uint4 bh1 = lds128(bb0 + 1024);
            uint4 bl1 = lds128(bb0 + 1536);
#pragma unroll
            for (int mi = 0; mi < 4; mi++) {
                unsigned ab = smem_u32 + buf * XG_ABUF
                            + (((mq * 4 + mi) * 2 + kt) * 2) * 512 + (lane << 4);
                uint4 ah = lds128(ab);
                uint4 al = lds128(ab + 512);
                mma16816(acc[mi][0], ah, bh0.x, bh0.y);
                mma16816(acc[mi][0], ah, bl0.x, bl0.y);
                mma16816(acc[mi][0], al, bh0.x, bh0.y);
                mma16816(acc[mi][1], ah, bh0.z, bh0.w);
                mma16816(acc[mi][1], ah, bl0.z, bl0.w);
                mma16816(acc[mi][1], al, bh0.z, bh0.w);
                mma16816(acc[mi][2], ah, bh1.x, bh1.y);
                mma16816(acc[mi][2], ah, bl1.x, bl1.y);
                mma16816(acc[mi][2], al, bh1.x, bh1.y);
                mma16816(acc[mi][3], ah, bh1.z, bh1.w);
                mma16816(acc[mi][3], ah, bl1.z, bl1.w);
                mma16816(acc[mi][3], al, bh1.z, bh1.w);
            }
        }
        __syncthreads();
    }

    const int g = lane >> 2, tq = lane & 3;
#pragma unroll
    for (int mi = 0; mi < 4; mi++) {
        int row = bx * 128 + mq * 64 + mi * 16 + g;
#pragma unroll
        for (int nj = 0; nj < 4; nj++) {
            int col = by * 128 + nq * 32 + nj * 8 + tq * 2;
            float b0 = bias[col], b1 = bias[col + 1];
            float* p0 = g_xp + (size_t)row * GG + col;
            float* p1 = g_xp + (size_t)(row + 8) * GG + col;
            *(float2*)p0 = make_float2(acc[mi][nj][0] + b0, acc[mi][nj][1] + b1);
            *(float2*)p1 = make_float2(acc[mi][nj][2] + b0, acc[mi][nj][3] + b1);
        }
    }
}

// ---------------------------------------------------------------------------
// Persistent recurrence kernel.
// Warp kh (0..7) computes full D[64x32] partial over ktiles ktg = c*8+kh.
// Smem:
//   [0, 65536)          A double buffer (2 x 8-ktile chunks) -- reused for
//                        8 partial-D regions [kh][64][34] f32 at end of step
//   [69632, 200704)     Wh B-fragments (hi/lo)
//   [200704, 209920)    xp staging [64][36] f32
// ---------------------------------------------------------------------------
#define ABUF_BYTES 32768
#define PART_STRIDE 34
#define PART_RB (64 * PART_STRIDE * 4)    // 8704 per region
#define WOFF 69632
#define XPOFF 200704
#define XP_STRIDE 36
#define SMEM_BYTES (XPOFF + 64 * XP_STRIDE * 4)   // 209920

__global__ __launch_bounds__(256, 1) void recurrence_kernel(const float* __restrict__ Wh) {
    extern __shared__ char smem[];
    const int tid  = threadIdx.x;
    const int blk  = blockIdx.x;
    const int kh   = tid >> 5;       // warp id = K-slice id
    const int lane = tid & 31;
    const unsigned smem_u32 = (unsigned)__cvta_generic_to_shared(smem);

    // one-time: stage Wh slice as B fragments (hi/lo bf16)
    for (int idx = tid; idx < 32 * 1024; idx += 256) {
        int k = idx >> 5, n = idx & 31;
        int gcol = ((n >> 3) << 10) + (blk << 3) + (n & 7);
        float w = Wh[(size_t)k * GG + gcol];
        __nv_bfloat16 hi = __float2bfloat16(w);
        __nv_bfloat16 lo = __float2bfloat16(w - __bfloat162float(hi));
        int kc = k & 15;
        int ln = ((n & 7) << 2) + ((kc & 7) >> 1);
        int by = (((n >> 3) & 1) << 3) + (((kc >> 3) & 1) << 2) + ((kc & 1) << 1);
        int base = WOFF + ((((k >> 4) << 1) + (n >> 4)) << 1) * 512 + (ln << 4) + by;
        *(__nv_bfloat16*)(smem + base)       = hi;
        *(__nv_bfloat16*)(smem + base + 512) = lo;
    }
    __syncthreads();

    const int ub = tid & 63;
    const int up = tid >> 6;
    float creg[2] = {0.f, 0.f};

    for (int t = 0; t < TT; t++) {
        const char* hsrc = (const char*)g_hstage[t & 1];

        // prefetch chunk 0 + xp[t] slice (same commit group)
        {
            const char* src = hsrc + tid * 16;
            unsigned dst = smem_u32 + tid * 16;
#pragma unroll
            for (int j = 0; j < 8; j++) cpasync16(dst + j * 4096, src + j * 4096);
            // xp: idx = tid*2 + {0,1}; b=idx>>3, gate=(idx>>1)&3, half=idx&1
#pragma unroll
            for (int e = 0; e < 2; e++) {
                int idx = tid * 2 + e;
                int b_ = idx >> 3, gate = (idx >> 1) & 3, half = idx & 1;
                const float* s = g_xp + ((size_t)t * BB + b_) * GG
                               + gate * HH + (blk << 3) + half * 4;
                unsigned d = smem_u32 + XPOFF
                           + (b_ * XP_STRIDE + gate * 8 + half * 4) * 4;
                cpasync16(d, s);
            }
            asm volatile("cp.async.commit_group;");
        }

        float acc[4][4][4];
#pragma unroll
        for (int i = 0; i < 4; i++)
#pragma unroll
            for (int j = 0; j < 4; j++)
#pragma unroll
                for (int q = 0; q < 4; q++) acc[i][j][q] = 0.f;

        for (int c = 0; c < 8; c++) {
            if (c < 7) {
                const char* src = hsrc + (size_t)(c + 1) * ABUF_BYTES + tid * 16;
                unsigned dst = smem_u32 + ((c + 1) & 1) * ABUF_BYTES + tid * 16;
#pragma unroll
                for (int j = 0; j < 8; j++) cpasync16(dst + j * 4096, src + j * 4096);
                asm volatile("cp.async.commit_group;");
                asm volatile("cp.async.wait_group 1;");
            } else {
                asm volatile("cp.async.wait_group 0;");
            }
            __syncthreads();

            // this warp's ktile within the chunk is local index kh
            const int ktg = c * 8 + kh;
            unsigned bb0 = smem_u32 + WOFF + ((ktg * 2 + 0) * 2) * 512 + (lane << 4);
            unsigned bb1 = smem_u32 + WOFF + ((ktg * 2 + 1) * 2) * 512 + (lane << 4);
            uint4 bh0 = lds128(bb0);
            uint4 bl0 = lds128(bb0 + 512);
            uint4 bh1 = lds128(bb1);
            uint4 bl1 = lds128(bb1 + 512);
#pragma unroll
            for (int mt = 0; mt < 4; mt++) {
                unsigned ab = smem_u32 + (c & 1) * ABUF_BYTES
                            + ((kh * 4 + mt) * 2) * 512 + (lane << 4);
                uint4 ah = lds128(ab);
                uint4 al = lds128(ab + 512);
                mma16816(acc[mt][0], ah, bh0.x, bh0.y);
                mma16816(acc[mt][0], ah, bl0.x, bl0.y);
                mma16816(acc[mt][0], al, bh0.x, bh0.y);
                mma16816(acc[mt][1], ah, bh0.z, bh0.w);
                mma16816(acc[mt][1], ah, bl0.z, bl0.w);
                mma16816(acc[mt][1], al, bh0.z, bh0.w);
                mma16816(acc[mt][2], ah, bh1.x, bh1.y);
                mma16816(acc[mt][2], ah, bl1.x, bl1.y);
                mma16816(acc[mt][2], al, bh1.x, bh1.y);
                mma16816(acc[mt][3], ah, bh1.z, bh1.w);
                mma16816(acc[mt][3], ah, bl1.z, bl1.w);
                mma16816(acc[mt][3], al, bh1.z, bh1.w);
            }
            __syncthreads();
        }

        // ---- write per-kh partial D into A region (now free) ----
        {
            float* P = (float*)(smem + kh * PART_RB);
            int g = lane >> 2, tq = lane & 3;
#pragma unroll
            for (int mt = 0; mt < 4; mt++) {
#pragma unroll
                for (int nj = 0; nj < 4; nj++) {
                    int row = mt * 16 + g;
                    int col = nj * 8 + tq * 2;
                    *(float2*)&P[row * PART_STRIDE + col] =
                        make_float2(acc[mt][nj][0], acc[mt][nj][1]);
                    *(float2*)&P[(row + 8) * PART_STRIDE + col] =
                        make_float2(acc[mt][nj][2], acc[mt][nj][3]);
                }
            }
        }
        __syncthreads();

        // ---- pointwise LSTM update ----
        {
            const float* xps = (const float*)(smem + XPOFF);
            char* hdst = (char*)g_hstage[(t + 1) & 1];
#pragma unroll
            for (int pi = 0; pi < 2; pi++) {
                int p = up + pi * 4;
                int unit = (blk << 3) + p;
                float gv[4];
#pragma unroll
                for (int type = 0; type < 4; type++) {
                    int n = type * 8 + p;
                    float s = xps[ub * XP_STRIDE + type * 8 + p];
#pragma unroll
                    for (int r = 0; r < 8; r++)
                        s += ((const float*)(smem + r * PART_RB))[ub * PART_STRIDE + n];
                    gv[type] = s;
                }
                float si = 1.f / (1.f + expf(-gv[0]));
                float sf = 1.f / (1.f + expf(-gv[1]));
                float tg = tanhf(gv[2]);
                float so = 1.f / (1.f + expf(-gv[3]));
                float cn = fmaf(sf, creg[pi], si * tg);
                creg[pi] = cn;
                float hn = so * tanhf(cn);

                int r = ub & 15, mt = ub >> 4;
                int kc = unit & 15, ktile = unit >> 4;
                int ln  = ((r & 7) << 2) + ((kc & 7) >> 1);
                int reg = (((kc >> 3) & 1) << 1) + ((r >> 3) & 1);
                int off = (((ktile << 2) + mt) << 1) * 512 + (ln << 4)
                        + (reg << 2) + ((kc & 1) << 1);
                __nv_bfloat16 hi = __float2bfloat16(hn);
                __nv_bfloat16 lo = __float2bfloat16(hn - __bfloat162float(hi));
                *(__nv_bfloat16*)(hdst + off)       = hi;
                *(__nv_bfloat16*)(hdst + off + 512) = lo;
                if (t == TT - 1) g_h[ub * HH + unit] = hn;
            }
        }

        // ---- two-level grid barrier ----
        __threadfence();
        __syncthreads();
        if (tid == 0) {
            unsigned* grp = &g_grp[(blk >> 3) * 32];
            atomicAdd(grp, 1u);
            if ((blk & 7) == 0) {
                unsigned gt = (unsigned)(8 * (t + 1));
                while (*(volatile unsigned*)grp < gt) { }
                atomicAdd(&g_bar, 1u);
            }
            unsigned tgt = (unsigned)(16 * (t + 1));
            while (*(volatile unsigned*)&g_bar < tgt) { }
        }
        __syncthreads();
    }
}

// ---------------------------------------------------------------------------
// classifier: 64 blocks (one per batch), 128 threads.
// ---------------------------------------------------------------------------
__global__ __launch_bounds__(128) void classifier_kernel(
        const float* __restrict__ Wd, const float* __restrict__ bd,
        float* __restrict__ out) {
    __shared__ float4 red[4];
    int b = blockIdx.x, tid = threadIdx.x;
    int lane = tid & 31, warp = tid >> 5;
    float4 a = make_float4(0.f, 0.f, 0.f, 0.f);
    for (int k = tid; k < HH; k += 128) {
        float h = g_h[b * HH + k];
        float4 w = *(const float4*)(Wd + k * CC);
        a.x = fmaf(h, w.x, a.x); a.y = fmaf(h, w.y, a.y);
        a.z = fmaf(h, w.z, a.z); a.w = fmaf(h, w.w, a.w);
    }
#pragma unroll
    for (int s = 16; s > 0; s >>= 1) {
        a.x += __shfl_xor_sync(0xffffffffu, a.x, s);
        a.y += __shfl_xor_sync(0xffffffffu, a.y, s);
        a.z += __shfl_xor_sync(0xffffffffu, a.z, s);
        a.w += __shfl_xor_sync(0xffffffffu, a.w, s);
    }
    if (lane == 0) red[warp] = a;
    __syncthreads();
    if (tid == 0) {
        float4 s = red[0];
        s.x += red[1].x + red[2].x + red[3].x;
        s.y += red[1].y + red[2].y + red[3].y;
        s.z += red[1].z + red[2].z + red[3].z;
        s.w += red[1].w + red[2].w + red[3].w;
        out[b * CC + 0] = s.x + bd[0];
        out[b * CC + 1] = s.y + bd[1];
        out[b * CC + 2] = s.z + bd[2];
        out[b * CC + 3] = s.w + bd[3];
    }
}

// ---------------------------------------------------------------------------
// launch: 6 graph nodes
// ---------------------------------------------------------------------------
extern "C" void kernel_launch(void* const* d_in, const int* in_sizes, int n_in,
                              void* d_out, int out_size) {
    const int*   tokens = (const int*)d_in[0];
    const float* emb    = (const float*)d_in[1];
    const float* Wi     = (const float*)d_in[2];
    const float* Wh     = (const float*)d_in[3];
    const float* bias   = (const float*)d_in[4];
    const float* Wd     = (const float*)d_in[5];
    const float* bd     = (const float*)d_in[6];
    float* out = (float*)d_out;

    cudaFuncSetAttribute(recurrence_kernel,
                         cudaFuncAttributeMaxDynamicSharedMemorySize, SMEM_BYTES);
    cudaFuncSetAttribute(xgemm_kernel,
                         cudaFuncAttributeMaxDynamicSharedMemorySize, XG_SMEM);

    init_kernel<<<64, 256>>>();
    conv_a_kernel<<<2048 * 32 / 8, 256>>>(tokens, emb);
    conv_b_kernel<<<32 * 256 / 8, 256>>>(Wi);

    dim3 xg(256, 32);
    xgemm_kernel<<<xg, 256, XG_SMEM>>>(bias);

    recurrence_kernel<<<NBLK, 256, SMEM_BYTES>>>(Wh);

    classifier_kernel<<<BB, 128>>>(Wd, bd, out);
}

// round 7
// speedup vs baseline: 1.5715x; 1.2960x over previous
#include <cuda_runtime.h>
#include <cuda_bf16.h>
#include <cuda_fp16.h>
#include <math.h>

#define BB 64
#define TT 512
#define EE 512
#define HH 1024
#define GG 4096   // 4*H
#define CC 4
#define NBLK 128  // persistent recurrence blocks

// ---------------------------------------------------------------------------
// Global scratch (static device arrays — no runtime allocation)
// ---------------------------------------------------------------------------
__device__ float g_xp[(size_t)TT * BB * GG];          // [T][B][4H] input projections
__device__ float g_h[BB * HH];                        // final hidden state
// h staged as fp16 MMA A-fragments: [buf][ktile 64][mtile 4][lane 32] x 16B
__device__ uint4 g_hstage[2][64 * 4 * 32];
__device__ unsigned g_bar;                            // global barrier counter

// xproj operands pre-converted to MMA fragment layout (bf16 hi/lo)
__device__ uint4 g_afrag[(size_t)2048 * 32 * 2 * 32];   // 64 MB
__device__ uint4 g_bfrag[(size_t)32 * 256 * 2 * 32];    // 8 MB

// ---------------------------------------------------------------------------
// helpers
// ---------------------------------------------------------------------------
__device__ __forceinline__ void cpasync16(unsigned dst, const void* src) {
    asm volatile("cp.async.cg.shared.global [%0], [%1], 16;" :: "r"(dst), "l"(src));
}
__device__ __forceinline__ uint4 lds128(unsigned addr) {
    uint4 v;
    asm volatile("ld.shared.v4.u32 {%0,%1,%2,%3}, [%4];"
                 : "=r"(v.x), "=r"(v.y), "=r"(v.z), "=r"(v.w) : "r"(addr));
    return v;
}
__device__ __forceinline__ void mma16816(float* d, const uint4& a, unsigned b0, unsigned b1) {
    asm volatile("mma.sync.aligned.m16n8k16.row.col.f32.bf16.bf16.f32 "
                 "{%0,%1,%2,%3}, {%4,%5,%6,%7}, {%8,%9}, {%0,%1,%2,%3};"
                 : "+f"(d[0]), "+f"(d[1]), "+f"(d[2]), "+f"(d[3])
                 : "r"(a.x), "r"(a.y), "r"(a.z), "r"(a.w), "r"(b0), "r"(b1));
}
__device__ __forceinline__ void mma16816h(float* d, const uint4& a, unsigned b0, unsigned b1) {
    asm volatile("mma.sync.aligned.m16n8k16.row.col.f32.f16.f16.f32 "
                 "{%0,%1,%2,%3}, {%4,%5,%6,%7}, {%8,%9}, {%0,%1,%2,%3};"
                 : "+f"(d[0]), "+f"(d[1]), "+f"(d[2]), "+f"(d[3])
                 : "r"(a.x), "r"(a.y), "r"(a.z), "r"(a.w), "r"(b0), "r"(b1));
}
__device__ __forceinline__ unsigned pack_hi(float x0, float x1) {
    unsigned h0 = (unsigned)__bfloat16_as_ushort(__float2bfloat16(x0));
    unsigned h1 = (unsigned)__bfloat16_as_ushort(__float2bfloat16(x1));
    return h0 | (h1 << 16);
}
__device__ __forceinline__ unsigned pack_lo(float x0, float x1) {
    float r0 = x0 - __bfloat162float(__float2bfloat16(x0));
    float r1 = x1 - __bfloat162float(__float2bfloat16(x1));
    unsigned h0 = (unsigned)__bfloat16_as_ushort(__float2bfloat16(r0));
    unsigned h1 = (unsigned)__bfloat16_as_ushort(__float2bfloat16(r1));
    return h0 | (h1 << 16);
}

// ---------------------------------------------------------------------------
// init
// ---------------------------------------------------------------------------
__global__ void init_kernel() {
    int i = blockIdx.x * blockDim.x + threadIdx.x;
    if (i == 0) g_bar = 0u;
    if (i < 64 * 4 * 32) g_hstage[0][i] = make_uint4(0u, 0u, 0u, 0u);
}

// ---------------------------------------------------------------------------
// conv_a: gather emb rows, convert to bf16 hi/lo A-fragment layout. (validated)
// ---------------------------------------------------------------------------
__global__ __launch_bounds__(256) void conv_a_kernel(
        const int* __restrict__ tokens, const float* __restrict__ emb) {
    int gw = (blockIdx.x * 256 + threadIdx.x) >> 5;
    int lane = threadIdx.x & 31;
    int mt = gw >> 5;          // 0..2047
    int kt = gw & 31;          // 0..31
    int t_ = mt >> 2;
    int b0_ = ((mt & 3) << 4) + (lane >> 2);
    int b1_ = b0_ + 8;
    const float* er0 = emb + (size_t)tokens[b0_ * TT + t_] * EE + kt * 16;
    const float* er1 = emb + (size_t)tokens[b1_ * TT + t_] * EE + kt * 16;

    unsigned hi[4], lo[4];
#pragma unroll
    for (int r2 = 0; r2 < 4; r2++) {
        const float* er = (r2 & 1) ? er1 : er0;
        int kc0 = ((lane & 3) << 1) + ((r2 >> 1) << 3);
        float x0 = er[kc0], x1 = er[kc0 + 1];
        hi[r2] = pack_hi(x0, x1);
        lo[r2] = pack_lo(x0, x1);
    }
    size_t base = ((size_t)(mt * 32 + kt) * 2) * 32 + lane;
    g_afrag[base]      = make_uint4(hi[0], hi[1], hi[2], hi[3]);
    g_afrag[base + 32] = make_uint4(lo[0], lo[1], lo[2], lo[3]);
}

// ---------------------------------------------------------------------------
// conv_b: Wi -> bf16 hi/lo B-fragment layout. (validated)
// ---------------------------------------------------------------------------
__global__ __launch_bounds__(256) void conv_b_kernel(const float* __restrict__ Wi) {
    int gw = (blockIdx.x * 256 + threadIdx.x) >> 5;
    int lane = threadIdx.x & 31;
    int kt = gw >> 8;          // 0..31
    int nt = gw & 255;         // 0..255

    unsigned hi[4], lo[4];
#pragma unroll
    for (int w = 0; w < 4; w++) {
        int n  = ((w >> 1) << 3) + (lane >> 2);
        int kc0 = ((lane & 3) << 1) + ((w & 1) << 3);
        const float* p = Wi + (size_t)(kt * 16 + kc0) * GG + nt * 16 + n;
        float x0 = p[0], x1 = p[GG];
        hi[w] = pack_hi(x0, x1);
        lo[w] = pack_lo(x0, x1);
    }
    size_t base = ((size_t)(kt * 256 + nt) * 2) * 32 + lane;
    g_bfrag[base]      = make_uint4(hi[0], hi[1], hi[2], hi[3]);
    g_bfrag[base + 32] = make_uint4(lo[0], lo[1], lo[2], lo[3]);
}

// ---------------------------------------------------------------------------
// xgemm: XP = X @ Wi + bias via bf16 split-3 MMA. 128x128 tile. (validated)
// ---------------------------------------------------------------------------
#define XG_ABUF 16384
#define XG_BOFF 32768
#define XG_SMEM 65536

__global__ __launch_bounds__(256) void xgemm_kernel(const float* __restrict__ bias) {
    extern __shared__ char smem[];
    const unsigned smem_u32 = (unsigned)__cvta_generic_to_shared(smem);
    const int tid = threadIdx.x;
    const int warp = tid >> 5, lane = tid & 31;
    const int mq = warp & 1;
    const int nq = warp >> 1;
    const int bx = blockIdx.x, by = blockIdx.y;

    const bool isA = tid < 128;
    const int amt = (tid & 127) >> 4;
    const int sub = tid & 15;

    float acc[4][4][4];
#pragma unroll
    for (int i = 0; i < 4; i++)
#pragma unroll
        for (int j = 0; j < 4; j++)
#pragma unroll
            for (int q = 0; q < 4; q++) acc[i][j][q] = 0.f;

#pragma unroll
    for (int j = 0; j < 8; j++) {
        int q = sub * 8 + j;
        int kt = q >> 6, hl = (q >> 5) & 1, ln = q & 31;
        unsigned dst; const uint4* src;
        if (isA) {
            dst = smem_u32 + ((amt * 2 + kt) * 2 + hl) * 512 + ln * 16;
            src = g_afrag + (((size_t)(bx * 8 + amt) * 32 + kt) * 2 + hl) * 32 + ln;
        } else {
            dst = smem_u32 + XG_BOFF + ((kt * 8 + amt) * 2 + hl) * 512 + ln * 16;
            src = g_bfrag + (((size_t)kt * 256 + (by * 8 + amt)) * 2 + hl) * 32 + ln;
        }
        cpasync16(dst, src);
    }
    asm volatile("cp.async.commit_group;");

    for (int c = 0; c < 16; c++) {
        if (c < 15) {
            int buf = (c + 1) & 1;
#pragma unroll
            for (int j = 0; j < 8; j++) {
                int q = sub * 8 + j;
                int kt = q >> 6, hl = (q >> 5) & 1, ln = q & 31;
                int ktg = (c + 1) * 2 + kt;
                unsigned dst; const uint4* src;
                if (isA) {
                    dst = smem_u32 + buf * XG_ABUF + ((amt * 2 + kt) * 2 + hl) * 512 + ln * 16;
                    src = g_afrag + (((size_t)(bx * 8 + amt) * 32 + ktg) * 2 + hl) * 32 + ln;
                } else {
                    dst = smem_u32 + XG_BOFF + buf * XG_ABUF + ((kt * 8 + amt) * 2 + hl) * 512 + ln * 16;
                    src = g_bfrag + (((size_t)ktg * 256 + (by * 8 + amt)) * 2 + hl) * 32 + ln;
                }
                cpasync16(dst, src);
            }
            asm volatile("cp.async.commit_group;");
            asm volatile("cp.async.wait_group 1;");
        } else {
            asm volatile("cp.async.wait_group 0;");
        }
        __syncthreads();

        int buf = c & 1;
#pragma unroll
        for (int kt = 0; kt < 2; kt++) {
            unsigned bb0 = smem_u32 + XG_BOFF + buf * XG_ABUF
                         + ((kt * 8 + nq * 2) * 2) * 512 + (lane << 4);
            uint4 bh0 = lds128(bb0);
            uint4 bl0 = lds128(bb0 + 512);
            uint4 bh1 = lds128(bb0 + 1024);
            uint4 bl1 = lds128(bb0 + 1536);
#pragma unroll
            for (int mi = 0; mi < 4; mi++) {
                unsigned ab = smem_u32 + buf * XG_ABUF
                            + (((mq * 4 + mi) * 2 + kt) * 2) * 512 + (lane << 4);
                uint4 ah = lds128(ab);
                uint4 al = lds128(ab + 512);
                mma16816(acc[mi][0], ah, bh0.x, bh0.y);
                mma16816(acc[mi][0], ah, bl0.x, bl0.y);
                mma16816(acc[mi][0], al, bh0.x, bh0.y);
                mma16816(acc[mi][1], ah, bh0.z, bh0.w);
                mma16816(acc[mi][1], ah, bl0.z, bl0.w);
                mma16816(acc[mi][1], al, bh0.z, bh0.w);
                mma16816(acc[mi][2], ah, bh1.x, bh1.y);
                mma16816(acc[mi][2], ah, bl1.x, bl1.y);
                mma16816(acc[mi][2], al, bh1.x, bh1.y);
                mma16816(acc[mi][3], ah, bh1.z, bh1.w);
                mma16816(acc[mi][3], ah, bl1.z, bl1.w);
                mma16816(acc[mi][3], al, bh1.z, bh1.w);
            }
        }
        __syncthreads();
    }

    const int g = lane >> 2, tq = lane & 3;
#pragma unroll
    for (int mi = 0; mi < 4; mi++) {
        int row = bx * 128 + mq * 64 + mi * 16 + g;
#pragma unroll
        for (int nj = 0; nj < 4; nj++) {
            int col = by * 128 + nq * 32 + nj * 8 + tq * 2;
            float b0 = bias[col], b1 = bias[col + 1];
            float* p0 = g_xp + (size_t)row * GG + col;
            float* p1 = g_xp + (size_t)(row + 8) * GG + col;
            *(float2*)p0 = make_float2(acc[mi][nj][0] + b0, acc[mi][nj][1] + b1);
            *(float2*)p1 = make_float2(acc[mi][nj][2] + b0, acc[mi][nj][3] + b1);
        }
    }
}

// ---------------------------------------------------------------------------
// Persistent recurrence kernel, fp16 h x (Wh_hi + Wh_lo) split-2.
// Warp kh (0..7) computes D[64x32] partial over ktiles ktg = c*8+kh.
// Smem:
//   [0, 32768)          A double buffer (2 x 8-ktile fp16 chunks of 16 KB);
//                        [0, 69632) reused for 8 partial-D regions [kh][64][34]
//   [69632, 200704)     Wh B-fragments (fp16 hi/lo)
//   [200704, 209920)    xp staging [64][36] f32
// ---------------------------------------------------------------------------
#define ABUF_BYTES 16384
#define PART_STRIDE 34
#define PART_RB (64 * PART_STRIDE * 4)    // 8704 per region
#define WOFF 69632
#define XPOFF 200704
#define XP_STRIDE 36
#define SMEM_BYTES (XPOFF + 64 * XP_STRIDE * 4)   // 209920

__global__ __launch_bounds__(256, 1) void recurrence_kernel(const float* __restrict__ Wh) {
    extern __shared__ char smem[];
    const int tid  = threadIdx.x;
    const int blk  = blockIdx.x;
    const int kh   = tid >> 5;       // warp id = K-slice id
    const int lane = tid & 31;
    const unsigned smem_u32 = (unsigned)__cvta_generic_to_shared(smem);

    // one-time: stage Wh slice as B fragments (fp16 hi/lo)
    for (int idx = tid; idx < 32 * 1024; idx += 256) {
        int k = idx >> 5, n = idx & 31;
        int gcol = ((n >> 3) << 10) + (blk << 3) + (n & 7);
        float w = Wh[(size_t)k * GG + gcol];
        __half hi = __float2half_rn(w);
        __half lo = __float2half_rn(w - __half2float(hi));
        int kc = k & 15;
        int ln = ((n & 7) << 2) + ((kc & 7) >> 1);
        int by = (((n >> 3) & 1) << 3) + (((kc >> 3) & 1) << 2) + ((kc & 1) << 1);
        int base = WOFF + ((((k >> 4) << 1) + (n >> 4)) << 1) * 512 + (ln << 4) + by;
        *(__half*)(smem + base)       = hi;
        *(__half*)(smem + base + 512) = lo;
    }
    __syncthreads();

    const int ub = tid & 63;
    const int up = tid >> 6;
    float creg[2] = {0.f, 0.f};

    for (int t = 0; t < TT; t++) {
        const char* hsrc = (const char*)g_hstage[t & 1];

        // prefetch chunk 0 (16 KB) + xp[t] slice (same commit group)
        {
            const char* src = hsrc + tid * 16;
            unsigned dst = smem_u32 + tid * 16;
#pragma unroll
            for (int j = 0; j < 4; j++) cpasync16(dst + j * 4096, src + j * 4096);
#pragma unroll
            for (int e = 0; e < 2; e++) {
                int idx = tid * 2 + e;
                int b_ = idx >> 3, gate = (idx >> 1) & 3, half = idx & 1;
                const float* s = g_xp + ((size_t)t * BB + b_) * GG
                               + gate * HH + (blk << 3) + half * 4;
                unsigned d = smem_u32 + XPOFF
                           + (b_ * XP_STRIDE + gate * 8 + half * 4) * 4;
                cpasync16(d, s);
            }
            asm volatile("cp.async.commit_group;");
        }

        float acc[4][4][4];
#pragma unroll
        for (int i = 0; i < 4; i++)
#pragma unroll
            for (int j = 0; j < 4; j++)
#pragma unroll
                for (int q = 0; q < 4; q++) acc[i][j][q] = 0.f;

        for (int c = 0; c < 8; c++) {
            if (c < 7) {
                const char* src = hsrc + (size_t)(c + 1) * ABUF_BYTES + tid * 16;
                unsigned dst = smem_u32 + ((c + 1) & 1) * ABUF_BYTES + tid * 16;
#pragma unroll
                for (int j = 0; j < 4; j++) cpasync16(dst + j * 4096, src + j * 4096);
                asm volatile("cp.async.commit_group;");
                asm volatile("cp.async.wait_group 1;");
            } else {
                asm volatile("cp.async.wait_group 0;");
            }
            __syncthreads();

            const int ktg = c * 8 + kh;
            unsigned bb0 = smem_u32 + WOFF + ((ktg * 2 + 0) * 2) * 512 + (lane << 4);
            unsigned bb1 = smem_u32 + WOFF + ((ktg * 2 + 1) * 2) * 512 + (lane << 4);
            uint4 bh0 = lds128(bb0);
            uint4 bl0 = lds128(bb0 + 512);
            uint4 bh1 = lds128(bb1);
            uint4 bl1 = lds128(bb1 + 512);
#pragma unroll
            for (int mt = 0; mt < 4; mt++) {
                unsigned ab = smem_u32 + (c & 1) * ABUF_BYTES
                            + (kh * 4 + mt) * 512 + (lane << 4);
                uint4 ah = lds128(ab);
                mma16816h(acc[mt][0], ah, bh0.x, bh0.y);
                mma16816h(acc[mt][0], ah, bl0.x, bl0.y);
                mma16816h(acc[mt][1], ah, bh0.z, bh0.w);
                mma16816h(acc[mt][1], ah, bl0.z, bl0.w);
                mma16816h(acc[mt][2], ah, bh1.x, bh1.y);
                mma16816h(acc[mt][2], ah, bl1.x, bl1.y);
                mma16816h(acc[mt][3], ah, bh1.z, bh1.w);
                mma16816h(acc[mt][3], ah, bl1.z, bl1.w);
            }
            __syncthreads();
        }

        // ---- write per-kh partial D into A region (now free) ----
        {
            float* P = (float*)(smem + kh * PART_RB);
            int g = lane >> 2, tq = lane & 3;
#pragma unroll
            for (int mt = 0; mt < 4; mt++) {
#pragma unroll
                for (int nj = 0; nj < 4; nj++) {
                    int row = mt * 16 + g;
                    int col = nj * 8 + tq * 2;
                    *(float2*)&P[row * PART_STRIDE + col] =
                        make_float2(acc[mt][nj][0], acc[mt][nj][1]);
                    *(float2*)&P[(row + 8) * PART_STRIDE + col] =
                        make_float2(acc[mt][nj][2], acc[mt][nj][3]);
                }
            }
        }
        __syncthreads();

        // ---- pointwise LSTM update ----
        {
            const float* xps = (const float*)(smem + XPOFF);
            char* hdst = (char*)g_hstage[(t + 1) & 1];
#pragma unroll
            for (int pi = 0; pi < 2; pi++) {
                int p = up + pi * 4;
                int unit = (blk << 3) + p;
                float gv[4];
#pragma unroll
                for (int type = 0; type < 4; type++) {
                    int n = type * 8 + p;
                    float s = xps[ub * XP_STRIDE + type * 8 + p];
#pragma unroll
                    for (int r = 0; r < 8; r++)
                        s += ((const float*)(smem + r * PART_RB))[ub * PART_STRIDE + n];
                    gv[type] = s;
                }
                float si = 1.f / (1.f + expf(-gv[0]));
                float sf = 1.f / (1.f + expf(-gv[1]));
                float tg = tanhf(gv[2]);
                float so = 1.f / (1.f + expf(-gv[3]));
                float cn = fmaf(sf, creg[pi], si * tg);
                creg[pi] = cn;
                float hn = so * tanhf(cn);

                int r = ub & 15, mt = ub >> 4;
                int kc = unit & 15, ktile = unit >> 4;
                int ln  = ((r & 7) << 2) + ((kc & 7) >> 1);
                int reg = (((kc >> 3) & 1) << 1) + ((r >> 3) & 1);
                int off = (ktile * 4 + mt) * 512 + (ln << 4)
                        + (reg << 2) + ((kc & 1) << 1);
                *(__half*)(hdst + off) = __float2half_rn(hn);
                if (t == TT - 1) g_h[ub * HH + unit] = hn;
            }
        }

        // ---- single-counter grid barrier with backoff ----
        __threadfence();
        __syncthreads();
        if (tid == 0) {
            atomicAdd(&g_bar, 1u);
            unsigned tgt = (unsigned)(NBLK * (t + 1));
            while (*((volatile unsigned*)&g_bar) < tgt) __nanosleep(32);
        }
        __syncthreads();
    }
}

// ---------------------------------------------------------------------------
// classifier: 64 blocks (one per batch), 128 threads.
// ---------------------------------------------------------------------------
__global__ __launch_bounds__(128) void classifier_kernel(
        const float* __restrict__ Wd, const float* __restrict__ bd,
        float* __restrict__ out) {
    __shared__ float4 red[4];
    int b = blockIdx.x, tid = threadIdx.x;
    int lane = tid & 31, warp = tid >> 5;
    float4 a = make_float4(0.f, 0.f, 0.f, 0.f);
    for (int k = tid; k < HH; k += 128) {
        float h = g_h[b * HH + k];
        float4 w = *(const float4*)(Wd + k * CC);
        a.x = fmaf(h, w.x, a.x); a.y = fmaf(h, w.y, a.y);
        a.z = fmaf(h, w.z, a.z); a.w = fmaf(h, w.w, a.w);
    }
#pragma unroll
    for (int s = 16; s > 0; s >>= 1) {
        a.x += __shfl_xor_sync(0xffffffffu, a.x, s);
        a.y += __shfl_xor_sync(0xffffffffu, a.y, s);
        a.z += __shfl_xor_sync(0xffffffffu, a.z, s);
        a.w += __shfl_xor_sync(0xffffffffu, a.w, s);
    }
    if (lane == 0) red[warp] = a;
    __syncthreads();
    if (tid == 0) {
        float4 s = red[0];
        s.x += red[1].x + red[2].x + red[3].x;
        s.y += red[1].y + red[2].y + red[3].y;
        s.z += red[1].z + red[2].z + red[3].z;
        s.w += red[1].w + red[2].w + red[3].w;
        out[b * CC + 0] = s.x + bd[0];
        out[b * CC + 1] = s.y + bd[1];
        out[b * CC + 2] = s.z + bd[2];
        out[b * CC + 3] = s.w + bd[3];
    }
}

// ---------------------------------------------------------------------------
// launch: 6 graph nodes
// ---------------------------------------------------------------------------
extern "C" void kernel_launch(void* const* d_in, const int* in_sizes, int n_in,
                              void* d_out, int out_size) {
    const int*   tokens = (const int*)d_in[0];
    const float* emb    = (const float*)d_in[1];
    const float* Wi     = (const float*)d_in[2];
    const float* Wh     = (const float*)d_in[3];
    const float* bias   = (const float*)d_in[4];
    const float* Wd     = (const float*)d_in[5];
    const float* bd     = (const float*)d_in[6];
    float* out = (float*)d_out;

    cudaFuncSetAttribute(recurrence_kernel,
                         cudaFuncAttributeMaxDynamicSharedMemorySize, SMEM_BYTES);
    cudaFuncSetAttribute(xgemm_kernel,
                         cudaFuncAttributeMaxDynamicSharedMemorySize, XG_SMEM);

    init_kernel<<<64, 256>>>();
    conv_a_kernel<<<2048 * 32 / 8, 256>>>(tokens, emb);
    conv_b_kernel<<<32 * 256 / 8, 256>>>(Wi);

    dim3 xg(256, 32);
    xgemm_kernel<<<xg, 256, XG_SMEM>>>(bias);

    recurrence_kernel<<<NBLK, 256, SMEM_BYTES>>>(Wh);

    classifier_kernel<<<BB, 128>>>(Wd, bd, out);
}